// round 13
// baseline (speedup 1.0000x reference)
#include <cuda_runtime.h>
#include <cstdint>

#define NB   8192
#define NOPT 16
#define DIM  768
#define F4_PER_ROW (DIM / 4)   // 192 float4 per row
#define MARGIN 0.3f
#define GRID (NB / 2)

// Scratch: per-sample partials + completion counter (deterministic reduction).
__device__ float    g_loss[NB];
__device__ int      g_cnt[NB];
__device__ unsigned cf_counter = 0;   // returns to 0 at end of every launch

// Triangular index within an 8-row block (closed form -> constant folds).
__device__ __forceinline__ constexpr int tri8(int i, int j) {
    return i * 8 - (i * (i - 1)) / 2 + (j - i);
}

__device__ __forceinline__ void fma4(float& a, const float4& u, const float4& v) {
    a = fmaf(u.x, v.x, a);
    a = fmaf(u.y, v.y, a);
    a = fmaf(u.z, v.z, a);
    a = fmaf(u.w, v.w, a);
}

__device__ __forceinline__ void cp_async16(uint32_t saddr, const void* gptr) {
    asm volatile("cp.async.cg.shared.global [%0], [%1], 16;" :: "r"(saddr), "l"(gptr));
}
__device__ __forceinline__ void cp_commit() {
    asm volatile("cp.async.commit_group;");
}
template <int N>
__device__ __forceinline__ void cp_wait() {
    asm volatile("cp.async.wait_group %0;" :: "n"(N));
}

__device__ __forceinline__ void shfl_reduce_store(float v, float* G, int i, int j, int lane) {
    v += __shfl_xor_sync(0xFFFFFFFFu, v, 16);
    v += __shfl_xor_sync(0xFFFFFFFFu, v, 8);
    v += __shfl_xor_sync(0xFFFFFFFFu, v, 4);
    v += __shfl_xor_sync(0xFFFFFFFFu, v, 2);
    v += __shfl_xor_sync(0xFFFFFFFFu, v, 1);
    if (lane == 0) {
        G[i * NOPT + j] = v;
        G[j * NOPT + i] = v;
    }
}

// One k-iteration of warp W's pair set, fed from the smem tile chunk
// t[row*32 + col] (16 rows x 32 float4 = this iter's slice of all rows).
//   W=0: intra rows 0-7 triangle (36) + cross i in 0..3 x j in 8..15 (32)
//   W=1: intra rows 8-15 triangle (36) + cross i in 4..7 x j in 8..15 (32)
template <int W>
__device__ __forceinline__ void compute_iter(const float4* __restrict__ t,
                                             float (&accT)[36], float (&accC)[32],
                                             int lane) {
    constexpr int R0 = W * 8;
    float4 x[8];
#pragma unroll
    for (int n = 0; n < 8; ++n) x[n] = t[(R0 + n) * 32 + lane];

#pragma unroll
    for (int i = 0; i < 8; ++i)
#pragma unroll
        for (int j = i; j < 8; ++j)
            fma4(accT[tri8(i, j)], x[i], x[j]);

    if (W == 0) {
#pragma unroll
        for (int jj = 0; jj < 8; ++jj) {
            const float4 bR = t[(8 + jj) * 32 + lane];
#pragma unroll
            for (int i = 0; i < 4; ++i)
                fma4(accC[i * 8 + jj], x[i], bR);
        }
    } else {
#pragma unroll
        for (int ii = 0; ii < 4; ++ii) {
            const float4 aR = t[(4 + ii) * 32 + lane];
#pragma unroll
            for (int jj = 0; jj < 8; ++jj)
                fma4(accC[ii * 8 + jj], aR, x[jj]);
        }
    }
}

template <int W>
__device__ __forceinline__ void reduce_all(float (&accT)[36], float (&accC)[32],
                                           float* G, int lane) {
    constexpr int R0 = W * 8;
#pragma unroll
    for (int i = 0; i < 8; ++i)
#pragma unroll
        for (int j = i; j < 8; ++j)
            shfl_reduce_store(accT[tri8(i, j)], G, R0 + i, R0 + j, lane);

    if (W == 0) {
#pragma unroll
        for (int i = 0; i < 4; ++i)
#pragma unroll
            for (int jj = 0; jj < 8; ++jj)
                shfl_reduce_store(accC[i * 8 + jj], G, i, 8 + jj, lane);
    } else {
#pragma unroll
        for (int ii = 0; ii < 4; ++ii)
#pragma unroll
            for (int jj = 0; jj < 8; ++jj)
                shfl_reduce_store(accC[ii * 8 + jj], G, 4 + ii, 8 + jj, lane);
    }
}

// 128 threads = 2 samples x 2 warps; cp.async double-buffered smem pipeline.
// 32KB tile smem/CTA, ~120 regs -> 4 CTAs/SM.
__global__ void __launch_bounds__(128, 4)
cf_fused(const float* __restrict__ emb, const long long* __restrict__ labels,
         float* __restrict__ out) {
    __shared__ __align__(16) float4 tile[2][2][16 * 32];  // [sample][buf][row*32+col]
    __shared__ float G[2][NOPT * NOPT];
    __shared__ float invn[2][NOPT];
    __shared__ int   lab[2][NOPT];
    __shared__ float ssum[4];
    __shared__ int   scnt[4];
    __shared__ int   s_last;

    const int tid  = threadIdx.x;
    const int half = tid >> 6;            // sample within CTA
    const int ht   = tid & 63;            // thread within sample group
    const int wis  = (tid >> 5) & 1;      // warp-in-sample 0..1
    const int lane = tid & 31;
    const int b    = blockIdx.x * 2 + half;

    if (ht < NOPT) lab[half][ht] = (int)labels[(size_t)b * NOPT + ht];

    const float4* base = reinterpret_cast<const float4*>(emb + (size_t)b * NOPT * DIM);

    // Stage chunk k into buffer bf: 16 rows x 32 float4 (8KB), 8 x 16B per thread.
    auto fetch = [&](int bf, int k) {
#pragma unroll
        for (int r = 0; r < 8; ++r) {
            const int c   = ht + 64 * r;      // 0..511
            const int row = c >> 5;
            const int col = c & 31;
            const uint32_t saddr =
                (uint32_t)__cvta_generic_to_shared(&tile[half][bf][c]);
            cp_async16(saddr, base + row * F4_PER_ROW + 32 * k + col);
        }
        cp_commit();
    };

    float accT[36] = {};
    float accC[32] = {};

    fetch(0, 0);
    fetch(1, 1);

#pragma unroll
    for (int k = 0; k < 6; ++k) {
        if (k < 5) cp_wait<1>(); else cp_wait<0>();
        __syncthreads();                       // chunk k visible CTA-wide

        const float4* t = tile[half][k & 1];
        if (wis == 0) compute_iter<0>(t, accT, accC, lane);
        else          compute_iter<1>(t, accT, accC, lane);

        __syncthreads();                       // all readers done -> refill safe
        if (k + 2 < 6) fetch(k & 1, k + 2);    // overlap fetch k+2 w/ compute k+1
    }

    if (wis == 0) reduce_all<0>(accT, accC, G[half], lane);
    else          reduce_all<1>(accT, accC, G[half], lane);
    __syncthreads();

    if (ht < NOPT) invn[half][ht] = rsqrtf(fmaxf(G[half][ht * NOPT + ht], 1e-24f));
    __syncthreads();

    if (ht < NOPT) {
        const int  n     = ht;
        const bool isPos = (lab[half][n] == 1);
        const bool isNeg = (lab[half][n] == 0);
        const unsigned posm = __ballot_sync(0x0000FFFFu, isPos) & 0xFFFFu;
        const unsigned negm = __ballot_sync(0x0000FFFFu, isNeg) & 0xFFFFu;
        const bool valid = (posm != 0u) && (negm != 0u);

        const float in_ = invn[half][n];
        float mx = -1e9f;   // NEG_INF sentinel, matches reference
#pragma unroll
        for (int m = 0; m < NOPT; ++m) {
            if (lab[half][m] == 0)
                mx = fmaxf(mx, G[half][n * NOPT + m] * in_ * invn[half][m]);
        }
        const float trip = fmaxf(mx + MARGIN, 0.0f);
        float contrib = (isPos && valid) ? trip : 0.0f;

        contrib += __shfl_xor_sync(0x0000FFFFu, contrib, 8);
        contrib += __shfl_xor_sync(0x0000FFFFu, contrib, 4);
        contrib += __shfl_xor_sync(0x0000FFFFu, contrib, 2);
        contrib += __shfl_xor_sync(0x0000FFFFu, contrib, 1);

        if (n == 0) {
            g_loss[b] = contrib;
            g_cnt[b]  = valid ? __popc(posm) : 0;
        }
    }

    // Publish then arrive; last CTA reduces (deterministic fixed order).
    if (ht == 0) __threadfence();
    __syncthreads();
    if (tid == 0) {
        const unsigned t = atomicAdd(&cf_counter, 1u);
        s_last = (t == GRID - 1);
    }
    __syncthreads();

    if (s_last) {
        __threadfence();   // order counter observation before partial reads
        float s = 0.0f;
        int   c = 0;
#pragma unroll 8
        for (int i = tid; i < NB; i += 128) {
            s += __ldcg(&g_loss[i]);
            c += __ldcg(&g_cnt[i]);
        }
#pragma unroll
        for (int off = 16; off > 0; off >>= 1) {
            s += __shfl_xor_sync(0xFFFFFFFFu, s, off);
            c += __shfl_xor_sync(0xFFFFFFFFu, c, off);
        }
        if (lane == 0) { ssum[tid >> 5] = s; scnt[tid >> 5] = c; }
        __syncthreads();
        if (tid == 0) {
            const float st = (ssum[0] + ssum[1]) + (ssum[2] + ssum[3]);
            const int   ct = (scnt[0] + scnt[1]) + (scnt[2] + scnt[3]);
            out[0] = st / (float)(ct > 0 ? ct : 1);
            cf_counter = 0;   // reset for next graph replay
        }
    }
}

extern "C" void kernel_launch(void* const* d_in, const int* in_sizes, int n_in,
                              void* d_out, int out_size) {
    const float*     emb    = (const float*)d_in[0];
    const long long* labels = (const long long*)d_in[1];
    float*           out    = (float*)d_out;

    cf_fused<<<GRID, 128>>>(emb, labels, out);
}

// round 14
// speedup vs baseline: 1.0574x; 1.0574x over previous
#include <cuda_runtime.h>

#define NB   8192
#define NOPT 16
#define DIM  768
#define F4_PER_ROW (DIM / 4)   // 192 float4 per row
#define MARGIN 0.3f

// Scratch: per-sample partials + completion counter (deterministic reduction).
__device__ float    g_loss[NB];
__device__ int      g_cnt[NB];
__device__ unsigned cf_counter = 0;   // returns to 0 at end of every launch

// Triangular index within a 4-row block (closed form -> constant folds).
__device__ __forceinline__ constexpr int tri4(int i, int j) {
    return i * 4 - (i * (i - 1)) / 2 + (j - i);
}

__device__ __forceinline__ void fma4(float& a, const float4& u, const float4& v) {
    a = fmaf(u.x, v.x, a);
    a = fmaf(u.y, v.y, a);
    a = fmaf(u.z, v.z, a);
    a = fmaf(u.w, v.w, a);
}

__device__ __forceinline__ void shfl_reduce_store(float v, float* G, int i, int j, int lane) {
    v += __shfl_xor_sync(0xFFFFFFFFu, v, 16);
    v += __shfl_xor_sync(0xFFFFFFFFu, v, 8);
    v += __shfl_xor_sync(0xFFFFFFFFu, v, 4);
    v += __shfl_xor_sync(0xFFFFFFFFu, v, 2);
    v += __shfl_xor_sync(0xFFFFFFFFu, v, 1);
    if (lane == 0) {
        G[i * NOPT + j] = v;
        G[j * NOPT + i] = v;
    }
}

// 4 warps per sample, 34 pairs each (~72 regs -> 24-28 warps/SM):
//   w0: tri(B0) + B0xB1(16)            + B0xB2 i in {0,1} (8)
//   w1: tri(B1) + B1xB2(16)            + B0xB2 i in {2,3} (8)
//   w2: tri(B2) + B2xB3(16)            + B0xB3 i in {0,1} (8)
//   w3: tri(B3) + B1xB3(16)            + B0xB3 i in {2,3} (8)
// Blocks Bn = rows 4n..4n+3. Warp W keeps block resident as x[4]; streamed
// rows are shared between the 16-pair and 8-pair sets where possible.
template <int W>
__device__ __forceinline__ void sample_work(const float4* __restrict__ base,
                                            float* __restrict__ G, int lane) {
    constexpr int R0 = 4 * W;   // resident block rows

    float accT[10] = {};
    float accP[16] = {};
    float accS[8]  = {};

    for (int k = 0; k < 6; ++k) {
        const float4* p0 = base + lane + 32 * k;

        float4 x[4];
#pragma unroll
        for (int n = 0; n < 4; ++n) x[n] = p0[(R0 + n) * F4_PER_ROW];

        // Extra streamed rows for the secondary (8-pair) set.
        float4 e0, e1;
        if (W == 1 || W == 3) { e0 = p0[2 * F4_PER_ROW]; e1 = p0[3 * F4_PER_ROW]; }
        if (W == 2)           { e0 = p0[0];              e1 = p0[1 * F4_PER_ROW]; }

        // Intra-block triangle (10 pairs).
#pragma unroll
        for (int i = 0; i < 4; ++i)
#pragma unroll
            for (int j = i; j < 4; ++j)
                fma4(accT[tri4(i, j)], x[i], x[j]);

        if (W == 0) {
            // Primary: B0 x B1
#pragma unroll
            for (int jr = 0; jr < 4; ++jr) {
                const float4 r = p0[(4 + jr) * F4_PER_ROW];
#pragma unroll
                for (int i = 0; i < 4; ++i) fma4(accP[i * 4 + jr], x[i], r);
            }
            // Secondary: rows {0,1} x B2
#pragma unroll
            for (int jr = 0; jr < 4; ++jr) {
                const float4 c = p0[(8 + jr) * F4_PER_ROW];
                fma4(accS[jr],     x[0], c);
                fma4(accS[4 + jr], x[1], c);
            }
        } else if (W == 1) {
            // Stream B2 once; feeds primary (B1 x B2) and secondary ({2,3} x B2).
#pragma unroll
            for (int jr = 0; jr < 4; ++jr) {
                const float4 c = p0[(8 + jr) * F4_PER_ROW];
#pragma unroll
                for (int i = 0; i < 4; ++i) fma4(accP[i * 4 + jr], x[i], c);
                fma4(accS[jr],     e0, c);
                fma4(accS[4 + jr], e1, c);
            }
        } else if (W == 2) {
            // Stream B3 once; feeds primary (B2 x B3) and secondary ({0,1} x B3).
#pragma unroll
            for (int jr = 0; jr < 4; ++jr) {
                const float4 d = p0[(12 + jr) * F4_PER_ROW];
#pragma unroll
                for (int i = 0; i < 4; ++i) fma4(accP[i * 4 + jr], x[i], d);
                fma4(accS[jr],     e0, d);
                fma4(accS[4 + jr], e1, d);
            }
        } else {
            // Primary: B1 x B3 (stream B1 rows; B3 resident).
#pragma unroll
            for (int ir = 0; ir < 4; ++ir) {
                const float4 a = p0[(4 + ir) * F4_PER_ROW];
#pragma unroll
                for (int jj = 0; jj < 4; ++jj) fma4(accP[ir * 4 + jj], a, x[jj]);
            }
            // Secondary: rows {2,3} x B3 (resident).
#pragma unroll
            for (int jj = 0; jj < 4; ++jj) {
                fma4(accS[jj],     e0, x[jj]);
                fma4(accS[4 + jj], e1, x[jj]);
            }
        }
    }

    // Cross-lane reduce + store (same shfl tree as all passing rounds).
#pragma unroll
    for (int i = 0; i < 4; ++i)
#pragma unroll
        for (int j = i; j < 4; ++j)
            shfl_reduce_store(accT[tri4(i, j)], G, R0 + i, R0 + j, lane);

    if (W == 0) {
#pragma unroll
        for (int i = 0; i < 4; ++i)
#pragma unroll
            for (int jr = 0; jr < 4; ++jr)
                shfl_reduce_store(accP[i * 4 + jr], G, i, 4 + jr, lane);
#pragma unroll
        for (int i2 = 0; i2 < 2; ++i2)
#pragma unroll
            for (int jr = 0; jr < 4; ++jr)
                shfl_reduce_store(accS[i2 * 4 + jr], G, i2, 8 + jr, lane);
    } else if (W == 1) {
#pragma unroll
        for (int i = 0; i < 4; ++i)
#pragma unroll
            for (int jr = 0; jr < 4; ++jr)
                shfl_reduce_store(accP[i * 4 + jr], G, 4 + i, 8 + jr, lane);
#pragma unroll
        for (int i2 = 0; i2 < 2; ++i2)
#pragma unroll
            for (int jr = 0; jr < 4; ++jr)
                shfl_reduce_store(accS[i2 * 4 + jr], G, 2 + i2, 8 + jr, lane);
    } else if (W == 2) {
#pragma unroll
        for (int i = 0; i < 4; ++i)
#pragma unroll
            for (int jr = 0; jr < 4; ++jr)
                shfl_reduce_store(accP[i * 4 + jr], G, 8 + i, 12 + jr, lane);
#pragma unroll
        for (int i2 = 0; i2 < 2; ++i2)
#pragma unroll
            for (int jr = 0; jr < 4; ++jr)
                shfl_reduce_store(accS[i2 * 4 + jr], G, i2, 12 + jr, lane);
    } else {
#pragma unroll
        for (int ir = 0; ir < 4; ++ir)
#pragma unroll
            for (int jj = 0; jj < 4; ++jj)
                shfl_reduce_store(accP[ir * 4 + jj], G, 4 + ir, 12 + jj, lane);
#pragma unroll
        for (int i2 = 0; i2 < 2; ++i2)
#pragma unroll
            for (int jj = 0; jj < 4; ++jj)
                shfl_reduce_store(accS[i2 * 4 + jj], G, 2 + i2, 12 + jj, lane);
    }
}

// 128 threads = 1 sample x 4 warps; ~72-85 regs -> 6-7 CTAs/SM = 24-28 warps/SM.
__global__ void __launch_bounds__(128, 6)
cf_fused(const float* __restrict__ emb, const long long* __restrict__ labels,
         float* __restrict__ out) {
    __shared__ float G[NOPT * NOPT];
    __shared__ float invn[NOPT];
    __shared__ int   lab[NOPT];
    __shared__ float ssum[4];
    __shared__ int   scnt[4];
    __shared__ int   s_last;

    const int tid  = threadIdx.x;
    const int w    = tid >> 5;
    const int lane = tid & 31;
    const int b    = blockIdx.x;

    if (tid < NOPT) lab[tid] = (int)labels[(size_t)b * NOPT + tid];

    const float4* base = reinterpret_cast<const float4*>(emb + (size_t)b * NOPT * DIM);

    switch (w) {
        case 0:  sample_work<0>(base, G, lane); break;
        case 1:  sample_work<1>(base, G, lane); break;
        case 2:  sample_work<2>(base, G, lane); break;
        default: sample_work<3>(base, G, lane); break;
    }
    __syncthreads();

    if (tid < NOPT) invn[tid] = rsqrtf(fmaxf(G[tid * NOPT + tid], 1e-24f));
    __syncthreads();

    if (tid < NOPT) {
        const int  n     = tid;
        const bool isPos = (lab[n] == 1);
        const bool isNeg = (lab[n] == 0);
        const unsigned posm = __ballot_sync(0x0000FFFFu, isPos) & 0xFFFFu;
        const unsigned negm = __ballot_sync(0x0000FFFFu, isNeg) & 0xFFFFu;
        const bool valid = (posm != 0u) && (negm != 0u);

        const float in_ = invn[n];
        float mx = -1e9f;   // NEG_INF sentinel, matches reference
#pragma unroll
        for (int m = 0; m < NOPT; ++m) {
            if (lab[m] == 0)
                mx = fmaxf(mx, G[n * NOPT + m] * in_ * invn[m]);
        }
        const float trip = fmaxf(mx + MARGIN, 0.0f);
        float contrib = (isPos && valid) ? trip : 0.0f;

        contrib += __shfl_xor_sync(0x0000FFFFu, contrib, 8);
        contrib += __shfl_xor_sync(0x0000FFFFu, contrib, 4);
        contrib += __shfl_xor_sync(0x0000FFFFu, contrib, 2);
        contrib += __shfl_xor_sync(0x0000FFFFu, contrib, 1);

        if (n == 0) {
            g_loss[b] = contrib;
            g_cnt[b]  = valid ? __popc(posm) : 0;
        }
    }

    // Publish then arrive; last CTA reduces (deterministic fixed order).
    if (tid == 0) __threadfence();
    __syncthreads();
    if (tid == 0) {
        const unsigned t = atomicAdd(&cf_counter, 1u);
        s_last = (t == NB - 1);
    }
    __syncthreads();

    if (s_last) {
        __threadfence();   // order counter observation before partial reads
        float s = 0.0f;
        int   c = 0;
#pragma unroll 8
        for (int i = tid; i < NB; i += 128) {
            s += __ldcg(&g_loss[i]);
            c += __ldcg(&g_cnt[i]);
        }
#pragma unroll
        for (int off = 16; off > 0; off >>= 1) {
            s += __shfl_xor_sync(0xFFFFFFFFu, s, off);
            c += __shfl_xor_sync(0xFFFFFFFFu, c, off);
        }
        if (lane == 0) { ssum[tid >> 5] = s; scnt[tid >> 5] = c; }
        __syncthreads();
        if (tid == 0) {
            const float st = (ssum[0] + ssum[1]) + (ssum[2] + ssum[3]);
            const int   ct = (scnt[0] + scnt[1]) + (scnt[2] + scnt[3]);
            out[0] = st / (float)(ct > 0 ? ct : 1);
            cf_counter = 0;   // reset for next graph replay
        }
    }
}

extern "C" void kernel_launch(void* const* d_in, const int* in_sizes, int n_in,
                              void* d_out, int out_size) {
    const float*     emb    = (const float*)d_in[0];
    const long long* labels = (const long long*)d_in[1];
    float*           out    = (float*)d_out;

    cf_fused<<<NB, 128>>>(emb, labels, out);
}

// round 16
// speedup vs baseline: 1.5674x; 1.4823x over previous
#include <cuda_runtime.h>
#include <cstdint>

#define NB     8192
#define NOPT   16
#define DIM    768
#define MARGIN 0.3f
#define KC     64                  // cols per chunk
#define NCH    (DIM / KC)          // 12 chunks
#define P      68                  // smem pitch in floats (4r+c distinct mod 32)
#define WPC    8                   // warps (= samples) per CTA
#define NCTA   (NB / WPC)          // 1024

__device__ float    g_loss[NB];
__device__ int      g_cnt[NB];
__device__ unsigned cf_counter = 0;   // returns to 0 at end of every launch

__device__ __forceinline__ float cvt_tf32(float x) {
    float r;
    asm("cvt.rna.tf32.f32 %0, %1;" : "=f"(r) : "f"(x));
    return r;
}

// D(16x8) += A(16x8,row) * B(8x8,col); tf32 in, f32 accum.
__device__ __forceinline__ void mma_16x8x8(float (&d)[4], const float (&a)[4],
                                           float b0, float b1) {
    asm volatile(
        "mma.sync.aligned.m16n8k8.row.col.f32.tf32.tf32.f32 "
        "{%0,%1,%2,%3}, {%4,%5,%6,%7}, {%8,%9}, {%0,%1,%2,%3};"
        : "+f"(d[0]), "+f"(d[1]), "+f"(d[2]), "+f"(d[3])
        : "f"(a[0]), "f"(a[1]), "f"(a[2]), "f"(a[3]), "f"(b0), "f"(b1));
}

// 256 threads = 8 warps; each warp owns one sample end-to-end. No CTA-wide
// syncs in the hot loop. Warp-private smem chunk (16 rows x 64 cols, pitch 68).
__global__ void __launch_bounds__(256)
cf_mma(const float* __restrict__ emb, const long long* __restrict__ labels,
       float* __restrict__ out) {
    __shared__ float buf[WPC][16 * P];   // 4352 B/warp -> 34.8 KB/CTA
    __shared__ float ssum[WPC];
    __shared__ int   scnt[WPC];
    __shared__ int   s_last;

    const int tid  = threadIdx.x;
    const int wid  = tid >> 5;
    const int lane = tid & 31;
    const int b    = blockIdx.x * WPC + wid;   // sample index

    float* wbuf = buf[wid];
    const float* gbase = emb + (size_t)b * NOPT * DIM;

    // Gmem staging mapping: iter t covers rows 2t, 2t+1; lane L -> float4 col.
    // u = L + 32t: row = u>>4, c4 = u&15 (cols 4*c4 .. 4*c4+3). Coalesced 256B.
    float4 stg[8];
    auto ldreg = [&](int k) {
#pragma unroll
        for (int t = 0; t < 8; ++t) {
            const int u = lane + 32 * t;
            const int row = u >> 4, c4 = u & 15;
            stg[t] = *reinterpret_cast<const float4*>(
                gbase + (size_t)row * DIM + k * KC + 4 * c4);
        }
    };

    const int r  = lane >> 2;       // frag row group 0..7
    const int cc = lane & 3;        // frag col 0..3

    float acc0[4] = {};             // D cols 0..7
    float acc1[4] = {};             // D cols 8..15

    ldreg(0);

#pragma unroll 1
    for (int k = 0; k < NCH; ++k) {
        // STS chunk k (float4; conflict-free contiguous-per-row pattern).
#pragma unroll
        for (int t = 0; t < 8; ++t) {
            const int u = lane + 32 * t;
            const int row = u >> 4, c4 = u & 15;
            *reinterpret_cast<float4*>(&wbuf[row * P + 4 * c4]) = stg[t];
        }
        __syncwarp();

        if (k + 1 < NCH) ldreg(k + 1);   // prefetch under compute

        // 8 k8-steps: a-frags double as b-frags (Gram symmetry).
#pragma unroll
        for (int s = 0; s < 8; ++s) {
            float a[4];
            a[0] = cvt_tf32(wbuf[r * P + 8 * s + cc]);
            a[1] = cvt_tf32(wbuf[(r + 8) * P + 8 * s + cc]);
            a[2] = cvt_tf32(wbuf[r * P + 8 * s + cc + 4]);
            a[3] = cvt_tf32(wbuf[(r + 8) * P + 8 * s + cc + 4]);
            mma_16x8x8(acc0, a, a[0], a[2]);   // n = rows 0..7
            mma_16x8x8(acc1, a, a[1], a[3]);   // n = rows 8..15
        }
        __syncwarp();                  // readers done before next STS
    }

    // Dump D (16x16) to smem (reuse chunk buffer; pitch 17).
    {
        float* G = wbuf;
        const int c2 = 2 * cc;
        G[r * 17 + c2]            = acc0[0];
        G[r * 17 + c2 + 1]        = acc0[1];
        G[(r + 8) * 17 + c2]      = acc0[2];
        G[(r + 8) * 17 + c2 + 1]  = acc0[3];
        G[r * 17 + 8 + c2]        = acc1[0];
        G[r * 17 + 8 + c2 + 1]    = acc1[1];
        G[(r + 8) * 17 + 8 + c2]      = acc1[2];
        G[(r + 8) * 17 + 8 + c2 + 1]  = acc1[3];
    }
    __syncwarp();

    // Scalar epilogue on lanes 0..15 (one lane per option row).
    if (lane < NOPT) {
        const float* G = wbuf;
        const int n = lane;
        const int labi = (int)labels[(size_t)b * NOPT + n];

        const float diag = G[n * 17 + n];
        const float invn = rsqrtf(fmaxf(diag, 1e-24f));

        const bool isPos = (labi == 1);
        const bool isNeg = (labi == 0);
        const unsigned posm = __ballot_sync(0x0000FFFFu, isPos) & 0xFFFFu;
        const unsigned negm = __ballot_sync(0x0000FFFFu, isNeg) & 0xFFFFu;
        const bool valid = (posm != 0u) && (negm != 0u);

        float mx = -1e9f;   // NEG_INF sentinel, matches reference
#pragma unroll
        for (int m = 0; m < NOPT; ++m) {
            const float innm = __shfl_sync(0x0000FFFFu, invn, m);
            const int   labm = __shfl_sync(0x0000FFFFu, labi, m);
            if (labm == 0) mx = fmaxf(mx, G[n * 17 + m] * invn * innm);
        }
        const float trip = fmaxf(mx + MARGIN, 0.0f);
        float contrib = (isPos && valid) ? trip : 0.0f;

        contrib += __shfl_xor_sync(0x0000FFFFu, contrib, 8);
        contrib += __shfl_xor_sync(0x0000FFFFu, contrib, 4);
        contrib += __shfl_xor_sync(0x0000FFFFu, contrib, 2);
        contrib += __shfl_xor_sync(0x0000FFFFu, contrib, 1);

        if (n == 0) {
            g_loss[b] = contrib;
            g_cnt[b]  = valid ? __popc(posm) : 0;
        }
    }

    // Publish, then one arrival per CTA; last CTA reduces deterministically.
    __threadfence();
    __syncthreads();
    if (tid == 0) {
        const unsigned t = atomicAdd(&cf_counter, 1u);
        s_last = (t == NCTA - 1);
    }
    __syncthreads();

    if (s_last) {
        __threadfence();
        float s = 0.0f;
        int   c = 0;
#pragma unroll 8
        for (int i = tid; i < NB; i += 256) {
            s += __ldcg(&g_loss[i]);
            c += __ldcg(&g_cnt[i]);
        }
#pragma unroll
        for (int off = 16; off > 0; off >>= 1) {
            s += __shfl_xor_sync(0xFFFFFFFFu, s, off);
            c += __shfl_xor_sync(0xFFFFFFFFu, c, off);
        }
        if (lane == 0) { ssum[wid] = s; scnt[wid] = c; }
        __syncthreads();
        if (tid == 0) {
            float st = 0.0f;
            int   ct = 0;
#pragma unroll
            for (int w = 0; w < WPC; ++w) { st += ssum[w]; ct += scnt[w]; }
            out[0] = st / (float)(ct > 0 ? ct : 1);
            cf_counter = 0;   // reset for next graph replay
        }
    }
}

extern "C" void kernel_launch(void* const* d_in, const int* in_sizes, int n_in,
                              void* d_out, int out_size) {
    const float*     emb    = (const float*)d_in[0];
    const long long* labels = (const long long*)d_in[1];
    float*           out    = (float*)d_out;

    cf_mma<<<NCTA, 256>>>(emb, labels, out);
}